// round 14
// baseline (speedup 1.0000x reference)
#include <cuda_runtime.h>
#include <cuda.h>
#include <cuda_fp16.h>
#include <cstdint>

#define IN_F   4096
#define OUT_F  4096
#define MROWS  8192          // B*S = 4*2048

#define BM 128
#define BN 128
#define BK 64                // halves per k-tile (128 B rows)
#define STAGES 3
#define KTILES (IN_F / BK)   // 64
#define NTILES ((MROWS / BM) * (OUT_F / BN))       // 2048
#define TILE_BYTES (BM * 128)                      // 16384 per matrix per stage
#define STAGE_BYTES (2 * TILE_BYTES)               // 32768 (A + B)
#define SMEM_HDR 1024
#define SMEM_BYTES (SMEM_HDR + STAGES * STAGE_BYTES)   // 99328

#define MB_FULL(s)  ((s) * 16)
#define MB_EMPTY(s) ((s) * 16 + 8)

// ---------------- scratch (no runtime allocation allowed) -------------------
__device__ __align__(1024) __half g_w16[(size_t)OUT_F * IN_F];   // 32 MB
__device__ __align__(1024) __half g_x16[(size_t)MROWS * IN_F];   // 64 MB

// ---------------- helpers ----------------
__device__ __forceinline__ uint32_t s2u(const void* p) {
    uint32_t a;
    asm("{ .reg .u64 t; cvta.to.shared.u64 t, %1; cvt.u32.u64 %0, t; }" : "=r"(a) : "l"(p));
    return a;
}
__device__ __forceinline__ void mbar_init(uint32_t m, uint32_t cnt) {
    asm volatile("mbarrier.init.shared.b64 [%0], %1;" :: "r"(m), "r"(cnt) : "memory");
}
__device__ __forceinline__ void mbar_arrive(uint32_t m) {
    asm volatile("{ .reg .b64 t; mbarrier.arrive.shared.b64 t, [%0]; }" :: "r"(m) : "memory");
}
__device__ __forceinline__ void mbar_expect_tx(uint32_t m, uint32_t bytes) {
    asm volatile("mbarrier.arrive.expect_tx.shared.b64 _, [%0], %1;" :: "r"(m), "r"(bytes) : "memory");
}
__device__ __forceinline__ void mbar_wait(uint32_t m, uint32_t parity) {
    asm volatile(
        "{\n\t.reg .pred P;\n\t"
        "WL_%=:\n\t"
        "mbarrier.try_wait.parity.acquire.cta.shared::cta.b64 P, [%0], %1, 0x989680;\n\t"
        "@P bra.uni WD_%=;\n\t"
        "bra.uni WL_%=;\n\t"
        "WD_%=:\n\t}"
        :: "r"(m), "r"(parity) : "memory");
}
__device__ __forceinline__ void tma_load_2d(uint32_t dst, const CUtensorMap* map,
                                            int cx, int cy, uint32_t mbar) {
    asm volatile(
        "cp.async.bulk.tensor.2d.shared::cta.global.tile.mbarrier::complete_tx::bytes "
        "[%0], [%1, {%2, %3}], [%4];"
        :: "r"(dst), "l"(map), "r"(cx), "r"(cy), "r"(mbar) : "memory");
}
__device__ __forceinline__ void ldsm_x4(uint32_t* r, uint32_t addr) {
    asm volatile("ldmatrix.sync.aligned.m8n8.x4.shared.b16 {%0,%1,%2,%3}, [%4];"
                 : "=r"(r[0]), "=r"(r[1]), "=r"(r[2]), "=r"(r[3]) : "r"(addr));
}
__device__ __forceinline__ void mma_f16(float* d, const uint32_t* a, const uint32_t* b) {
    asm volatile(
        "mma.sync.aligned.m16n8k16.row.col.f32.f16.f16.f32 "
        "{%0,%1,%2,%3}, {%4,%5,%6,%7}, {%8,%9}, {%0,%1,%2,%3};"
        : "+f"(d[0]), "+f"(d[1]), "+f"(d[2]), "+f"(d[3])
        : "r"(a[0]), "r"(a[1]), "r"(a[2]), "r"(a[3]), "r"(b[0]), "r"(b[1]));
}

// tile id -> (m_base, n_base) with GM=8 supertile swizzle
__device__ __forceinline__ void tile_bases(int t, int& mb, int& nb) {
    const int NT = OUT_F / BN;        // 32
    const int GM = 8;
    int grp = t / (GM * NT);
    int inb = t % (GM * NT);
    mb = (grp * GM + (inb % GM)) * BM;
    nb = (inb / GM) * BN;
}

// ------------- kernel 1: fused preprocessing (wdeq || xcvt) -----------------
#define NB_W ((size_t)OUT_F * IN_F / 2048)   // 8192
#define NB_X ((size_t)MROWS * IN_F / 2048)   // 16384

__global__ void __launch_bounds__(256) prep_kernel(const float* __restrict__ cent,
                                                   const int* __restrict__ idx,
                                                   const float* __restrict__ x,
                                                   __half* __restrict__ w,
                                                   __half* __restrict__ y) {
    int t = threadIdx.x;
    if (blockIdx.x < NB_W) {
        __shared__ __half c[256];
        c[t] = __float2half_rn(cent[t]);
        __syncthreads();
        size_t i = ((size_t)blockIdx.x * 256 + t) * 8;
        int4 v0 = *reinterpret_cast<const int4*>(idx + i);
        int4 v1 = *reinterpret_cast<const int4*>(idx + i + 4);
        __half h[8];
        h[0] = c[v0.x]; h[1] = c[v0.y]; h[2] = c[v0.z]; h[3] = c[v0.w];
        h[4] = c[v1.x]; h[5] = c[v1.y]; h[6] = c[v1.z]; h[7] = c[v1.w];
        *reinterpret_cast<uint4*>(w + i) = *reinterpret_cast<uint4*>(h);
    } else {
        size_t i = ((size_t)(blockIdx.x - NB_W) * 256 + t) * 8;
        float4 v0 = *reinterpret_cast<const float4*>(x + i);
        float4 v1 = *reinterpret_cast<const float4*>(x + i + 4);
        __half h[8];
        h[0] = __float2half_rn(v0.x); h[1] = __float2half_rn(v0.y);
        h[2] = __float2half_rn(v0.z); h[3] = __float2half_rn(v0.w);
        h[4] = __float2half_rn(v1.x); h[5] = __float2half_rn(v1.y);
        h[6] = __float2half_rn(v1.z); h[7] = __float2half_rn(v1.w);
        *reinterpret_cast<uint4*>(y + i) = *reinterpret_cast<uint4*>(h);
    }
}

// ------- kernel 2: persistent fp16 mma GEMM, TMA + mbarrier pipeline --------
__global__ void __launch_bounds__(256, 2)
gemm_f16(const __grid_constant__ CUtensorMap tma_a,
         const __grid_constant__ CUtensorMap tma_b,
         float* __restrict__ out) {
    extern __shared__ char smem_raw[];
    const uint32_t sb = s2u(smem_raw);
    const uint32_t data0 = sb + SMEM_HDR;

    const int tid = threadIdx.x;
    const int wid = tid >> 5, lane = tid & 31;
    const int warp_m = wid >> 2;      // 0..1 -> 64 rows
    const int warp_n = wid & 3;       // 0..3 -> 32 cols

    if (tid == 0) {
        #pragma unroll
        for (int s = 0; s < STAGES; s++) {
            mbar_init(sb + MB_FULL(s), 1);    // expect_tx arrival
            mbar_init(sb + MB_EMPTY(s), 8);   // one arrive per warp
        }
    }
    __syncthreads();

    // ldmatrix lane addressing (SW128 swizzled, 128 B rows)
    const int l7 = lane & 7;
    const int a_row = warp_m * 64 + l7 + ((lane >> 3) & 1) * 8;
    const int b_row = warp_n * 32 + l7 + ((lane >> 4) & 1) * 8;
    const uint32_t a_rowoff = (uint32_t)(a_row * 128);
    const uint32_t b_rowoff = (uint32_t)(b_row * 128);
    const uint32_t a_t = (uint32_t)(((lane >> 4) & 1) * 16) ^ (uint32_t)((a_row & 7) * 16);
    const uint32_t b_t = (uint32_t)(((lane >> 3) & 1) * 16) ^ (uint32_t)((b_row & 7) * 16);

    float acc[4][4][4];
    #pragma unroll
    for (int mi = 0; mi < 4; mi++)
        #pragma unroll
        for (int ni = 0; ni < 4; ni++)
            #pragma unroll
            for (int e = 0; e < 4; e++) acc[mi][ni][e] = 0.f;

    const int GRID = gridDim.x;

    // ---- producer state (used by tid 0 only) ----
    int p_t = blockIdx.x;             // tile currently being produced
    int p_kt = 0;
    int p_mb, p_nb;
    tile_bases(p_t, p_mb, p_nb);
    int ps = 0, pph = 1;

    auto produce_raw = [&](int s) {
        uint32_t a_dst = data0 + (uint32_t)(s * STAGE_BYTES);
        mbar_expect_tx(sb + MB_FULL(s), STAGE_BYTES);
        tma_load_2d(a_dst, &tma_a, p_kt * BK, p_mb, sb + MB_FULL(s));
        tma_load_2d(a_dst + TILE_BYTES, &tma_b, p_kt * BK, p_nb, sb + MB_FULL(s));
        if (++p_kt == KTILES) {
            p_kt = 0;
            p_t += GRID;
            if (p_t < NTILES) tile_bases(p_t, p_mb, p_nb);
        }
    };
    auto produce_next = [&]() {
        if (p_t < NTILES) {
            mbar_wait(sb + MB_EMPTY(ps), pph);
            produce_raw(ps);
            if (++ps == STAGES) { ps = 0; pph ^= 1; }
        }
    };

    // prologue: fill 2 stages (fresh empty barriers pass at parity 1)
    if (tid == 0) { produce_next(); produce_next(); }

    int cs = 0, cph = 0;              // consumer full-cursor

    for (int t = blockIdx.x; t < NTILES; t += GRID) {
        int m_base, n_base;
        tile_bases(t, m_base, n_base);

        for (int kt = 0; kt < KTILES; kt++) {
            if (tid == 0) produce_next();

            mbar_wait(sb + MB_FULL(cs), cph);

            const uint32_t a_stage = data0 + (uint32_t)(cs * STAGE_BYTES);
            const uint32_t b_stage = a_stage + TILE_BYTES;
            uint32_t a[4][4], b[2][4];
            #pragma unroll
            for (int k0 = 0; k0 < 4; k0++) {
                const uint32_t KB = (uint32_t)(k0 * 32);
                #pragma unroll
                for (int mi = 0; mi < 4; mi++)
                    ldsm_x4(a[mi], a_stage + a_rowoff + (uint32_t)(mi * 16 * 128) + (KB ^ a_t));
                ldsm_x4(b[0], b_stage + b_rowoff + (KB ^ b_t));
                ldsm_x4(b[1], b_stage + b_rowoff + (uint32_t)(16 * 128) + (KB ^ b_t));
                if (k0 == 3 && lane == 0) mbar_arrive(sb + MB_EMPTY(cs));  // early release
                #pragma unroll
                for (int mi = 0; mi < 4; mi++) {
                    mma_f16(acc[mi][0], a[mi], &b[0][0]);
                    mma_f16(acc[mi][1], a[mi], &b[0][2]);
                    mma_f16(acc[mi][2], a[mi], &b[1][0]);
                    mma_f16(acc[mi][3], a[mi], &b[1][2]);
                }
            }
            if (++cs == STAGES) { cs = 0; cph ^= 1; }
        }

        // epilogue for this tile (pipeline keeps running for the next tile)
        #pragma unroll
        for (int mi = 0; mi < 4; mi++) {
            int r0 = m_base + warp_m * 64 + mi * 16 + (lane >> 2);
            #pragma unroll
            for (int ni = 0; ni < 4; ni++) {
                int c = n_base + warp_n * 32 + ni * 8 + 2 * (lane & 3);
                float2 v0 = make_float2(acc[mi][ni][0], acc[mi][ni][1]);
                float2 v1 = make_float2(acc[mi][ni][2], acc[mi][ni][3]);
                *reinterpret_cast<float2*>(out + (size_t)r0 * OUT_F + c) = v0;
                *reinterpret_cast<float2*>(out + (size_t)(r0 + 8) * OUT_F + c) = v1;
                acc[mi][ni][0] = 0.f; acc[mi][ni][1] = 0.f;
                acc[mi][ni][2] = 0.f; acc[mi][ni][3] = 0.f;
            }
        }
    }
}

// ---------------- host ----------------
typedef CUresult (*EncodeFn)(CUtensorMap*, CUtensorMapDataType, cuuint32_t, void*,
                             const cuuint64_t*, const cuuint64_t*, const cuuint32_t*,
                             const cuuint32_t*, CUtensorMapInterleave, CUtensorMapSwizzle,
                             CUtensorMapL2promotion, CUtensorMapFloatOOBfill);

extern "C" void kernel_launch(void* const* d_in, const int* in_sizes, int n_in,
                              void* d_out, int out_size) {
    const float* x    = (const float*)d_in[0];   // [8192, 4096] fp32
    const float* cent = (const float*)d_in[1];   // [256, 1] fp32
    const int*   idx  = (const int*)d_in[2];     // [4096, 4096] int32
    float* out = (float*)d_out;                  // [8192, 4096] fp32

    void* w16_ptr = nullptr; cudaGetSymbolAddress(&w16_ptr, g_w16);
    void* x16_ptr = nullptr; cudaGetSymbolAddress(&x16_ptr, g_x16);

    prep_kernel<<<(unsigned)(NB_W + NB_X), 256>>>(cent, idx, x,
                                                  (__half*)w16_ptr, (__half*)x16_ptr);

    void* fn = nullptr;
    cudaDriverEntryPointQueryResult qr;
    cudaGetDriverEntryPointByVersion("cuTensorMapEncodeTiled", &fn, 12000,
                                     cudaEnableDefault, &qr);
    EncodeFn enc = (EncodeFn)fn;

    CUtensorMap ta, tb;
    {
        cuuint64_t dims[2]    = {IN_F, MROWS};
        cuuint64_t strides[1] = {(cuuint64_t)IN_F * 2};
        cuuint32_t box[2]     = {BK, BM};
        cuuint32_t es[2]      = {1, 1};
        enc(&ta, CU_TENSOR_MAP_DATA_TYPE_UINT16, 2, x16_ptr, dims, strides, box, es,
            CU_TENSOR_MAP_INTERLEAVE_NONE, CU_TENSOR_MAP_SWIZZLE_128B,
            CU_TENSOR_MAP_L2_PROMOTION_L2_128B, CU_TENSOR_MAP_FLOAT_OOB_FILL_NONE);
    }
    {
        cuuint64_t dims[2]    = {IN_F, OUT_F};
        cuuint64_t strides[1] = {(cuuint64_t)IN_F * 2};
        cuuint32_t box[2]     = {BK, BN};
        cuuint32_t es[2]      = {1, 1};
        enc(&tb, CU_TENSOR_MAP_DATA_TYPE_UINT16, 2, w16_ptr, dims, strides, box, es,
            CU_TENSOR_MAP_INTERLEAVE_NONE, CU_TENSOR_MAP_SWIZZLE_128B,
            CU_TENSOR_MAP_L2_PROMOTION_L2_128B, CU_TENSOR_MAP_FLOAT_OOB_FILL_NONE);
    }

    int sms = 148;
    cudaDeviceGetAttribute(&sms, cudaDevAttrMultiProcessorCount, 0);
    cudaFuncSetAttribute(gemm_f16, cudaFuncAttributeMaxDynamicSharedMemorySize, SMEM_BYTES);
    gemm_f16<<<2 * sms, 256, SMEM_BYTES>>>(ta, tb, out);
}

// round 15
// speedup vs baseline: 1.0378x; 1.0378x over previous
#include <cuda_runtime.h>
#include <cuda.h>
#include <cuda_fp16.h>
#include <cstdint>

#define IN_F   4096
#define OUT_F  4096
#define MROWS  8192          // B*S = 4*2048

#define BM 128
#define BN 128
#define BK 64                // halves per k-tile (128 B rows)
#define STAGES 3
#define KTILES (IN_F / BK)   // 64
#define TILE_BYTES (BM * 128)                      // 16384 per matrix per stage
#define STAGE_BYTES (2 * TILE_BYTES)               // 32768 (A + B)
#define SMEM_HDR 1024
#define SMEM_BYTES (SMEM_HDR + STAGES * STAGE_BYTES)   // 99328

#define MB_FULL(s)  ((s) * 16)
#define MB_EMPTY(s) ((s) * 16 + 8)

// ---------------- scratch (no runtime allocation allowed) -------------------
__device__ __align__(1024) __half g_w16[(size_t)OUT_F * IN_F];   // 32 MB
__device__ __align__(1024) __half g_x16[(size_t)MROWS * IN_F];   // 64 MB

// ---------------- helpers ----------------
__device__ __forceinline__ uint32_t s2u(const void* p) {
    uint32_t a;
    asm("{ .reg .u64 t; cvta.to.shared.u64 t, %1; cvt.u32.u64 %0, t; }" : "=r"(a) : "l"(p));
    return a;
}
__device__ __forceinline__ void mbar_init(uint32_t m, uint32_t cnt) {
    asm volatile("mbarrier.init.shared.b64 [%0], %1;" :: "r"(m), "r"(cnt) : "memory");
}
__device__ __forceinline__ void mbar_arrive(uint32_t m) {
    asm volatile("{ .reg .b64 t; mbarrier.arrive.shared.b64 t, [%0]; }" :: "r"(m) : "memory");
}
__device__ __forceinline__ void mbar_expect_tx(uint32_t m, uint32_t bytes) {
    asm volatile("mbarrier.arrive.expect_tx.shared.b64 _, [%0], %1;" :: "r"(m), "r"(bytes) : "memory");
}
__device__ __forceinline__ void mbar_wait(uint32_t m, uint32_t parity) {
    asm volatile(
        "{\n\t.reg .pred P;\n\t"
        "WL_%=:\n\t"
        "mbarrier.try_wait.parity.acquire.cta.shared::cta.b64 P, [%0], %1, 0x989680;\n\t"
        "@P bra.uni WD_%=;\n\t"
        "bra.uni WL_%=;\n\t"
        "WD_%=:\n\t}"
        :: "r"(m), "r"(parity) : "memory");
}
__device__ __forceinline__ void tma_load_2d(uint32_t dst, const CUtensorMap* map,
                                            int cx, int cy, uint32_t mbar) {
    asm volatile(
        "cp.async.bulk.tensor.2d.shared::cta.global.tile.mbarrier::complete_tx::bytes "
        "[%0], [%1, {%2, %3}], [%4];"
        :: "r"(dst), "l"(map), "r"(cx), "r"(cy), "r"(mbar) : "memory");
}
__device__ __forceinline__ void ldsm_x4(uint32_t* r, uint32_t addr) {
    asm volatile("ldmatrix.sync.aligned.m8n8.x4.shared.b16 {%0,%1,%2,%3}, [%4];"
                 : "=r"(r[0]), "=r"(r[1]), "=r"(r[2]), "=r"(r[3]) : "r"(addr));
}
__device__ __forceinline__ void mma_f16(float* d, const uint32_t* a, const uint32_t* b) {
    asm volatile(
        "mma.sync.aligned.m16n8k16.row.col.f32.f16.f16.f32 "
        "{%0,%1,%2,%3}, {%4,%5,%6,%7}, {%8,%9}, {%0,%1,%2,%3};"
        : "+f"(d[0]), "+f"(d[1]), "+f"(d[2]), "+f"(d[3])
        : "r"(a[0]), "r"(a[1]), "r"(a[2]), "r"(a[3]), "r"(b[0]), "r"(b[1]));
}

// ------------- kernel 1: fused preprocessing (wdeq || xcvt), 16/thread ------
#define NB_W ((size_t)OUT_F * IN_F / 4096)   // 4096
#define NB_X ((size_t)MROWS * IN_F / 4096)   // 8192

__global__ void __launch_bounds__(256) prep_kernel(const float* __restrict__ cent,
                                                   const int* __restrict__ idx,
                                                   const float* __restrict__ x,
                                                   __half* __restrict__ w,
                                                   __half* __restrict__ y) {
    int t = threadIdx.x;
    if (blockIdx.x < NB_W) {
        __shared__ __half c[256];
        c[t] = __float2half_rn(cent[t]);
        __syncthreads();
        size_t i = ((size_t)blockIdx.x * 256 + t) * 16;
        int4 v0 = *reinterpret_cast<const int4*>(idx + i);
        int4 v1 = *reinterpret_cast<const int4*>(idx + i + 4);
        int4 v2 = *reinterpret_cast<const int4*>(idx + i + 8);
        int4 v3 = *reinterpret_cast<const int4*>(idx + i + 12);
        __half h[16];
        h[0]  = c[v0.x]; h[1]  = c[v0.y]; h[2]  = c[v0.z]; h[3]  = c[v0.w];
        h[4]  = c[v1.x]; h[5]  = c[v1.y]; h[6]  = c[v1.z]; h[7]  = c[v1.w];
        h[8]  = c[v2.x]; h[9]  = c[v2.y]; h[10] = c[v2.z]; h[11] = c[v2.w];
        h[12] = c[v3.x]; h[13] = c[v3.y]; h[14] = c[v3.z]; h[15] = c[v3.w];
        *reinterpret_cast<uint4*>(w + i)     = *reinterpret_cast<uint4*>(h);
        *reinterpret_cast<uint4*>(w + i + 8) = *reinterpret_cast<uint4*>(h + 8);
    } else {
        size_t i = ((size_t)(blockIdx.x - NB_W) * 256 + t) * 16;
        float4 v0 = *reinterpret_cast<const float4*>(x + i);
        float4 v1 = *reinterpret_cast<const float4*>(x + i + 4);
        float4 v2 = *reinterpret_cast<const float4*>(x + i + 8);
        float4 v3 = *reinterpret_cast<const float4*>(x + i + 12);
        __half h[16];
        h[0]  = __float2half_rn(v0.x); h[1]  = __float2half_rn(v0.y);
        h[2]  = __float2half_rn(v0.z); h[3]  = __float2half_rn(v0.w);
        h[4]  = __float2half_rn(v1.x); h[5]  = __float2half_rn(v1.y);
        h[6]  = __float2half_rn(v1.z); h[7]  = __float2half_rn(v1.w);
        h[8]  = __float2half_rn(v2.x); h[9]  = __float2half_rn(v2.y);
        h[10] = __float2half_rn(v2.z); h[11] = __float2half_rn(v2.w);
        h[12] = __float2half_rn(v3.x); h[13] = __float2half_rn(v3.y);
        h[14] = __float2half_rn(v3.z); h[15] = __float2half_rn(v3.w);
        *reinterpret_cast<uint4*>(y + i)     = *reinterpret_cast<uint4*>(h);
        *reinterpret_cast<uint4*>(y + i + 8) = *reinterpret_cast<uint4*>(h + 8);
    }
}

// ---------------- kernel 2: fp16 mma GEMM, TMA + mbarrier pipeline ----------
// out[m,n] = sum_k X[m,k] * W[n,k]
__global__ void __launch_bounds__(256, 2)
gemm_f16(const __grid_constant__ CUtensorMap tma_a,
         const __grid_constant__ CUtensorMap tma_b,
         float* __restrict__ out) {
    extern __shared__ char smem_raw[];
    const uint32_t sb = s2u(smem_raw);
    const uint32_t data0 = sb + SMEM_HDR;

    const int tid = threadIdx.x;
    const int wid = tid >> 5, lane = tid & 31;
    const int warp_m = wid >> 2;      // 0..1 -> 64 rows
    const int warp_n = wid & 3;       // 0..3 -> 32 cols

    if (tid == 0) {
        #pragma unroll
        for (int s = 0; s < STAGES; s++) {
            mbar_init(sb + MB_FULL(s), 1);    // expect_tx arrival
            mbar_init(sb + MB_EMPTY(s), 8);   // lane 0 of each warp arrives
        }
    }
    __syncthreads();

    // grid swizzle: 8 M-tiles per supertile column (L2 reuse of W)
    const int NT = OUT_F / BN;        // 32
    const int GM = 8;
    int bid = blockIdx.x;
    int grp = bid / (GM * NT);
    int inb = bid % (GM * NT);
    int m_tile = grp * GM + (inb % GM);
    int n_tile = inb / GM;
    const int m_base = m_tile * BM;
    const int n_base = n_tile * BN;

    // ldmatrix lane addressing (SW128 swizzled, 128 B rows)
    const int l7 = lane & 7;
    const int a_row = warp_m * 64 + l7 + ((lane >> 3) & 1) * 8;
    const int b_row = warp_n * 32 + l7 + ((lane >> 4) & 1) * 8;
    const uint32_t a_rowoff = (uint32_t)(a_row * 128);
    const uint32_t b_rowoff = (uint32_t)(b_row * 128);
    const uint32_t a_t = (uint32_t)(((lane >> 4) & 1) * 16) ^ (uint32_t)((a_row & 7) * 16);
    const uint32_t b_t = (uint32_t)(((lane >> 3) & 1) * 16) ^ (uint32_t)((b_row & 7) * 16);

    float acc[4][4][4];
    #pragma unroll
    for (int mi = 0; mi < 4; mi++)
        #pragma unroll
        for (int ni = 0; ni < 4; ni++)
            #pragma unroll
            for (int e = 0; e < 4; e++) acc[mi][ni][e] = 0.f;

    auto produce = [&](int kt, int s) {      // tid 0 only
        uint32_t a_dst = data0 + (uint32_t)(s * STAGE_BYTES);
        mbar_expect_tx(sb + MB_FULL(s), STAGE_BYTES);
        tma_load_2d(a_dst, &tma_a, kt * BK, m_base, sb + MB_FULL(s));
        tma_load_2d(a_dst + TILE_BYTES, &tma_b, kt * BK, n_base, sb + MB_FULL(s));
    };

    // prologue: fill stages 0 and 1 (fresh empty barriers: parity 1 passes)
    if (tid == 0) {
        mbar_wait(sb + MB_EMPTY(0), 1);
        produce(0, 0);
        mbar_wait(sb + MB_EMPTY(1), 1);
        produce(1, 1);
    }

    int ps = 2, pph = 1;      // producer empty-cursor
    int cs = 0, cph = 0;      // consumer full-cursor

    for (int kt = 0; kt < KTILES; kt++) {
        if (tid == 0 && kt + 2 < KTILES) {
            mbar_wait(sb + MB_EMPTY(ps), pph);
            produce(kt + 2, ps);
        }
        if (kt + 2 < KTILES) {
            if (++ps == STAGES) { ps = 0; pph ^= 1; }
        }

        mbar_wait(sb + MB_FULL(cs), cph);

        const uint32_t a_stage = data0 + (uint32_t)(cs * STAGE_BYTES);
        const uint32_t b_stage = a_stage + TILE_BYTES;
        uint32_t a[4][4], b[2][4];
        #pragma unroll
        for (int k0 = 0; k0 < 4; k0++) {
            const uint32_t KB = (uint32_t)(k0 * 32);
            #pragma unroll
            for (int mi = 0; mi < 4; mi++)
                ldsm_x4(a[mi], a_stage + a_rowoff + (uint32_t)(mi * 16 * 128) + (KB ^ a_t));
            ldsm_x4(b[0], b_stage + b_rowoff + (KB ^ b_t));
            ldsm_x4(b[1], b_stage + b_rowoff + (uint32_t)(16 * 128) + (KB ^ b_t));
            if (k0 == 3 && lane == 0) mbar_arrive(sb + MB_EMPTY(cs));  // early release
            #pragma unroll
            for (int mi = 0; mi < 4; mi++) {
                mma_f16(acc[mi][0], a[mi], &b[0][0]);
                mma_f16(acc[mi][1], a[mi], &b[0][2]);
                mma_f16(acc[mi][2], a[mi], &b[1][0]);
                mma_f16(acc[mi][3], a[mi], &b[1][2]);
            }
        }
        if (++cs == STAGES) { cs = 0; cph ^= 1; }
    }

    // epilogue: direct STG.64
    #pragma unroll
    for (int mi = 0; mi < 4; mi++) {
        int r0 = m_base + warp_m * 64 + mi * 16 + (lane >> 2);
        #pragma unroll
        for (int ni = 0; ni < 4; ni++) {
            int c = n_base + warp_n * 32 + ni * 8 + 2 * (lane & 3);
            float2 v0 = make_float2(acc[mi][ni][0], acc[mi][ni][1]);
            float2 v1 = make_float2(acc[mi][ni][2], acc[mi][ni][3]);
            *reinterpret_cast<float2*>(out + (size_t)r0 * OUT_F + c) = v0;
            *reinterpret_cast<float2*>(out + (size_t)(r0 + 8) * OUT_F + c) = v1;
        }
    }
}

// ---------------- host ----------------
typedef CUresult (*EncodeFn)(CUtensorMap*, CUtensorMapDataType, cuuint32_t, void*,
                             const cuuint64_t*, const cuuint64_t*, const cuuint32_t*,
                             const cuuint32_t*, CUtensorMapInterleave, CUtensorMapSwizzle,
                             CUtensorMapL2promotion, CUtensorMapFloatOOBfill);

extern "C" void kernel_launch(void* const* d_in, const int* in_sizes, int n_in,
                              void* d_out, int out_size) {
    const float* x    = (const float*)d_in[0];   // [8192, 4096] fp32
    const float* cent = (const float*)d_in[1];   // [256, 1] fp32
    const int*   idx  = (const int*)d_in[2];     // [4096, 4096] int32
    float* out = (float*)d_out;                  // [8192, 4096] fp32

    void* w16_ptr = nullptr; cudaGetSymbolAddress(&w16_ptr, g_w16);
    void* x16_ptr = nullptr; cudaGetSymbolAddress(&x16_ptr, g_x16);

    prep_kernel<<<(unsigned)(NB_W + NB_X), 256>>>(cent, idx, x,
                                                  (__half*)w16_ptr, (__half*)x16_ptr);

    void* fn = nullptr;
    cudaDriverEntryPointQueryResult qr;
    cudaGetDriverEntryPointByVersion("cuTensorMapEncodeTiled", &fn, 12000,
                                     cudaEnableDefault, &qr);
    EncodeFn enc = (EncodeFn)fn;

    CUtensorMap ta, tb;
    {
        cuuint64_t dims[2]    = {IN_F, MROWS};
        cuuint64_t strides[1] = {(cuuint64_t)IN_F * 2};
        cuuint32_t box[2]     = {BK, BM};
        cuuint32_t es[2]      = {1, 1};
        enc(&ta, CU_TENSOR_MAP_DATA_TYPE_UINT16, 2, x16_ptr, dims, strides, box, es,
            CU_TENSOR_MAP_INTERLEAVE_NONE, CU_TENSOR_MAP_SWIZZLE_128B,
            CU_TENSOR_MAP_L2_PROMOTION_L2_128B, CU_TENSOR_MAP_FLOAT_OOB_FILL_NONE);
    }
    {
        cuuint64_t dims[2]    = {IN_F, OUT_F};
        cuuint64_t strides[1] = {(cuuint64_t)IN_F * 2};
        cuuint32_t box[2]     = {BK, BN};
        cuuint32_t es[2]      = {1, 1};
        enc(&tb, CU_TENSOR_MAP_DATA_TYPE_UINT16, 2, w16_ptr, dims, strides, box, es,
            CU_TENSOR_MAP_INTERLEAVE_NONE, CU_TENSOR_MAP_SWIZZLE_128B,
            CU_TENSOR_MAP_L2_PROMOTION_L2_128B, CU_TENSOR_MAP_FLOAT_OOB_FILL_NONE);
    }

    cudaFuncSetAttribute(gemm_f16, cudaFuncAttributeMaxDynamicSharedMemorySize, SMEM_BYTES);
    int grid = (MROWS / BM) * (OUT_F / BN);   // 64 * 32 = 2048
    gemm_f16<<<grid, 256, SMEM_BYTES>>>(ta, tb, out);
}

// round 16
// speedup vs baseline: 1.0395x; 1.0017x over previous
#include <cuda_runtime.h>
#include <cuda.h>
#include <cuda_fp16.h>
#include <cstdint>

#define IN_F   4096
#define OUT_F  4096
#define MROWS  8192          // B*S = 4*2048

#define BM 128
#define BN 128
#define BK 64                // halves per k-tile (128 B rows)
#define STAGES 3
#define KTILES (IN_F / BK)   // 64
#define TILE_BYTES (BM * 128)                      // 16384 per matrix per stage
#define STAGE_BYTES (2 * TILE_BYTES)               // 32768 (A + B)
#define SMEM_HDR 1024
#define SMEM_BYTES (SMEM_HDR + STAGES * STAGE_BYTES)   // 99328

#define MB_FULL(s)  ((s) * 16)
#define MB_EMPTY(s) ((s) * 16 + 8)

// ---------------- scratch (no runtime allocation allowed) -------------------
__device__ __align__(1024) __half g_w16[(size_t)OUT_F * IN_F];   // 32 MB
__device__ __align__(1024) __half g_x16[(size_t)MROWS * IN_F];   // 64 MB

// ---------------- helpers ----------------
__device__ __forceinline__ uint32_t s2u(const void* p) {
    uint32_t a;
    asm("{ .reg .u64 t; cvta.to.shared.u64 t, %1; cvt.u32.u64 %0, t; }" : "=r"(a) : "l"(p));
    return a;
}
__device__ __forceinline__ void mbar_init(uint32_t m, uint32_t cnt) {
    asm volatile("mbarrier.init.shared.b64 [%0], %1;" :: "r"(m), "r"(cnt) : "memory");
}
__device__ __forceinline__ void mbar_arrive(uint32_t m) {
    asm volatile("{ .reg .b64 t; mbarrier.arrive.shared.b64 t, [%0]; }" :: "r"(m) : "memory");
}
__device__ __forceinline__ void mbar_expect_tx(uint32_t m, uint32_t bytes) {
    asm volatile("mbarrier.arrive.expect_tx.shared.b64 _, [%0], %1;" :: "r"(m), "r"(bytes) : "memory");
}
__device__ __forceinline__ void mbar_wait(uint32_t m, uint32_t parity) {
    asm volatile(
        "{\n\t.reg .pred P;\n\t"
        "WL_%=:\n\t"
        "mbarrier.try_wait.parity.acquire.cta.shared::cta.b64 P, [%0], %1, 0x989680;\n\t"
        "@P bra.uni WD_%=;\n\t"
        "bra.uni WL_%=;\n\t"
        "WD_%=:\n\t}"
        :: "r"(m), "r"(parity) : "memory");
}
// relaxed wait: ONLY for the producer's empty-wait (post-wait accesses are
// async-proxy TMA, ordered by the TMA unit itself; no generic smem access)
__device__ __forceinline__ void mbar_wait_relaxed(uint32_t m, uint32_t parity) {
    asm volatile(
        "{\n\t.reg .pred P;\n\t"
        "WL_%=:\n\t"
        "mbarrier.try_wait.parity.relaxed.cta.shared::cta.b64 P, [%0], %1, 0x989680;\n\t"
        "@P bra.uni WD_%=;\n\t"
        "bra.uni WL_%=;\n\t"
        "WD_%=:\n\t}"
        :: "r"(m), "r"(parity) : "memory");
}
__device__ __forceinline__ void tma_load_2d(uint32_t dst, const CUtensorMap* map,
                                            int cx, int cy, uint32_t mbar) {
    asm volatile(
        "cp.async.bulk.tensor.2d.shared::cta.global.tile.mbarrier::complete_tx::bytes "
        "[%0], [%1, {%2, %3}], [%4];"
        :: "r"(dst), "l"(map), "r"(cx), "r"(cy), "r"(mbar) : "memory");
}
__device__ __forceinline__ void ldsm_x4(uint32_t* r, uint32_t addr) {
    asm volatile("ldmatrix.sync.aligned.m8n8.x4.shared.b16 {%0,%1,%2,%3}, [%4];"
                 : "=r"(r[0]), "=r"(r[1]), "=r"(r[2]), "=r"(r[3]) : "r"(addr));
}
__device__ __forceinline__ void mma_f16(float* d, const uint32_t* a, const uint32_t* b) {
    asm volatile(
        "mma.sync.aligned.m16n8k16.row.col.f32.f16.f16.f32 "
        "{%0,%1,%2,%3}, {%4,%5,%6,%7}, {%8,%9}, {%0,%1,%2,%3};"
        : "+f"(d[0]), "+f"(d[1]), "+f"(d[2]), "+f"(d[3])
        : "r"(a[0]), "r"(a[1]), "r"(a[2]), "r"(a[3]), "r"(b[0]), "r"(b[1]));
}

// ------------- kernel 1: fused preprocessing (wdeq || xcvt), 16/thread ------
#define NB_W ((size_t)OUT_F * IN_F / 4096)   // 4096
#define NB_X ((size_t)MROWS * IN_F / 4096)   // 8192

__global__ void __launch_bounds__(256) prep_kernel(const float* __restrict__ cent,
                                                   const int* __restrict__ idx,
                                                   const float* __restrict__ x,
                                                   __half* __restrict__ w,
                                                   __half* __restrict__ y) {
    int t = threadIdx.x;
    if (blockIdx.x < NB_W) {
        __shared__ __half c[256];
        c[t] = __float2half_rn(cent[t]);
        __syncthreads();
        size_t i = ((size_t)blockIdx.x * 256 + t) * 16;
        int4 v0 = *reinterpret_cast<const int4*>(idx + i);
        int4 v1 = *reinterpret_cast<const int4*>(idx + i + 4);
        int4 v2 = *reinterpret_cast<const int4*>(idx + i + 8);
        int4 v3 = *reinterpret_cast<const int4*>(idx + i + 12);
        __half h[16];
        h[0]  = c[v0.x]; h[1]  = c[v0.y]; h[2]  = c[v0.z]; h[3]  = c[v0.w];
        h[4]  = c[v1.x]; h[5]  = c[v1.y]; h[6]  = c[v1.z]; h[7]  = c[v1.w];
        h[8]  = c[v2.x]; h[9]  = c[v2.y]; h[10] = c[v2.z]; h[11] = c[v2.w];
        h[12] = c[v3.x]; h[13] = c[v3.y]; h[14] = c[v3.z]; h[15] = c[v3.w];
        *reinterpret_cast<uint4*>(w + i)     = *reinterpret_cast<uint4*>(h);
        *reinterpret_cast<uint4*>(w + i + 8) = *reinterpret_cast<uint4*>(h + 8);
    } else {
        size_t i = ((size_t)(blockIdx.x - NB_W) * 256 + t) * 16;
        float4 v0 = *reinterpret_cast<const float4*>(x + i);
        float4 v1 = *reinterpret_cast<const float4*>(x + i + 4);
        float4 v2 = *reinterpret_cast<const float4*>(x + i + 8);
        float4 v3 = *reinterpret_cast<const float4*>(x + i + 12);
        __half h[16];
        h[0]  = __float2half_rn(v0.x); h[1]  = __float2half_rn(v0.y);
        h[2]  = __float2half_rn(v0.z); h[3]  = __float2half_rn(v0.w);
        h[4]  = __float2half_rn(v1.x); h[5]  = __float2half_rn(v1.y);
        h[6]  = __float2half_rn(v1.z); h[7]  = __float2half_rn(v1.w);
        h[8]  = __float2half_rn(v2.x); h[9]  = __float2half_rn(v2.y);
        h[10] = __float2half_rn(v2.z); h[11] = __float2half_rn(v2.w);
        h[12] = __float2half_rn(v3.x); h[13] = __float2half_rn(v3.y);
        h[14] = __float2half_rn(v3.z); h[15] = __float2half_rn(v3.w);
        *reinterpret_cast<uint4*>(y + i)     = *reinterpret_cast<uint4*>(h);
        *reinterpret_cast<uint4*>(y + i + 8) = *reinterpret_cast<uint4*>(h + 8);
    }
}

// ---------------- kernel 2: fp16 mma GEMM, TMA + mbarrier pipeline ----------
// out[m,n] = sum_k X[m,k] * W[n,k]
__global__ void __launch_bounds__(256, 2)
gemm_f16(const __grid_constant__ CUtensorMap tma_a,
         const __grid_constant__ CUtensorMap tma_b,
         float* __restrict__ out) {
    extern __shared__ char smem_raw[];
    const uint32_t sb = s2u(smem_raw);
    const uint32_t data0 = sb + SMEM_HDR;

    const int tid = threadIdx.x;
    const int wid = tid >> 5, lane = tid & 31;
    const int warp_m = wid >> 2;      // 0..1 -> 64 rows
    const int warp_n = wid & 3;       // 0..3 -> 32 cols

    if (tid == 0) {
        #pragma unroll
        for (int s = 0; s < STAGES; s++) {
            mbar_init(sb + MB_FULL(s), 1);    // expect_tx arrival
            mbar_init(sb + MB_EMPTY(s), 8);   // lane 0 of each warp arrives
        }
    }
    __syncthreads();

    // grid swizzle: 8 M-tiles per supertile column (L2 reuse of W)
    const int NT = OUT_F / BN;        // 32
    const int GM = 8;
    int bid = blockIdx.x;
    int grp = bid / (GM * NT);
    int inb = bid % (GM * NT);
    int m_tile = grp * GM + (inb % GM);
    int n_tile = inb / GM;
    const int m_base = m_tile * BM;
    const int n_base = n_tile * BN;

    // ldmatrix lane addressing (SW128 swizzled, 128 B rows)
    const int l7 = lane & 7;
    const int a_row = warp_m * 64 + l7 + ((lane >> 3) & 1) * 8;
    const int b_row = warp_n * 32 + l7 + ((lane >> 4) & 1) * 8;
    const uint32_t a_rowoff = (uint32_t)(a_row * 128);
    const uint32_t b_rowoff = (uint32_t)(b_row * 128);
    const uint32_t a_t = (uint32_t)(((lane >> 4) & 1) * 16) ^ (uint32_t)((a_row & 7) * 16);
    const uint32_t b_t = (uint32_t)(((lane >> 3) & 1) * 16) ^ (uint32_t)((b_row & 7) * 16);

    // hoist per-k-step swizzled offsets (loop-invariant across ktiles)
    uint32_t a_ko[4], b_ko[4];
    #pragma unroll
    for (int k0 = 0; k0 < 4; k0++) {
        a_ko[k0] = a_rowoff + ((uint32_t)(k0 * 32) ^ a_t);
        b_ko[k0] = b_rowoff + ((uint32_t)(k0 * 32) ^ b_t);
    }

    float acc[4][4][4];
    #pragma unroll
    for (int mi = 0; mi < 4; mi++)
        #pragma unroll
        for (int ni = 0; ni < 4; ni++)
            #pragma unroll
            for (int e = 0; e < 4; e++) acc[mi][ni][e] = 0.f;

    auto produce = [&](int kt, int s) {      // tid 0 only
        uint32_t a_dst = data0 + (uint32_t)(s * STAGE_BYTES);
        mbar_expect_tx(sb + MB_FULL(s), STAGE_BYTES);
        tma_load_2d(a_dst, &tma_a, kt * BK, m_base, sb + MB_FULL(s));
        tma_load_2d(a_dst + TILE_BYTES, &tma_b, kt * BK, n_base, sb + MB_FULL(s));
    };

    // prologue: fill stages 0 and 1 (fresh empty barriers: parity 1 passes)
    if (tid == 0) {
        mbar_wait_relaxed(sb + MB_EMPTY(0), 1);
        produce(0, 0);
        mbar_wait_relaxed(sb + MB_EMPTY(1), 1);
        produce(1, 1);
    }

    int ps = 2, pph = 1;      // producer empty-cursor
    int cs = 0, cph = 0;      // consumer full-cursor

    for (int kt = 0; kt < KTILES; kt++) {
        if (tid == 0 && kt + 2 < KTILES) {
            mbar_wait_relaxed(sb + MB_EMPTY(ps), pph);
            produce(kt + 2, ps);
        }
        if (kt + 2 < KTILES) {
            if (++ps == STAGES) { ps = 0; pph ^= 1; }
        }

        mbar_wait(sb + MB_FULL(cs), cph);

        const uint32_t a_stage = data0 + (uint32_t)(cs * STAGE_BYTES);
        const uint32_t b_stage = a_stage + TILE_BYTES;
        uint32_t a[4][4], b[2][4];
        #pragma unroll
        for (int k0 = 0; k0 < 4; k0++) {
            #pragma unroll
            for (int mi = 0; mi < 4; mi++)
                ldsm_x4(a[mi], a_stage + a_ko[k0] + (uint32_t)(mi * 16 * 128));
            ldsm_x4(b[0], b_stage + b_ko[k0]);
            ldsm_x4(b[1], b_stage + b_ko[k0] + (uint32_t)(16 * 128));
            #pragma unroll
            for (int mi = 0; mi < 4; mi++) {
                mma_f16(acc[mi][0], a[mi], &b[0][0]);
                mma_f16(acc[mi][1], a[mi], &b[0][2]);
                mma_f16(acc[mi][2], a[mi], &b[1][0]);
                mma_f16(acc[mi][3], a[mi], &b[1][2]);
            }
        }
        // RACE-FREE release: by here every LDSM for this stage has completed
        // (in-order issue + MMA operand scoreboards gate the last MMA's issue).
        if (lane == 0) mbar_arrive(sb + MB_EMPTY(cs));

        if (++cs == STAGES) { cs = 0; cph ^= 1; }
    }

    // epilogue: direct STG.64
    #pragma unroll
    for (int mi = 0; mi < 4; mi++) {
        int r0 = m_base + warp_m * 64 + mi * 16 + (lane >> 2);
        #pragma unroll
        for (int ni = 0; ni < 4; ni++) {
            int c = n_base + warp_n * 32 + ni * 8 + 2 * (lane & 3);
            float2 v0 = make_float2(acc[mi][ni][0], acc[mi][ni][1]);
            float2 v1 = make_float2(acc[mi][ni][2], acc[mi][ni][3]);
            *reinterpret_cast<float2*>(out + (size_t)r0 * OUT_F + c) = v0;
            *reinterpret_cast<float2*>(out + (size_t)(r0 + 8) * OUT_F + c) = v1;
        }
    }
}

// ---------------- host ----------------
typedef CUresult (*EncodeFn)(CUtensorMap*, CUtensorMapDataType, cuuint32_t, void*,
                             const cuuint64_t*, const cuuint64_t*, const cuuint32_t*,
                             const cuuint32_t*, CUtensorMapInterleave, CUtensorMapSwizzle,
                             CUtensorMapL2promotion, CUtensorMapFloatOOBfill);

extern "C" void kernel_launch(void* const* d_in, const int* in_sizes, int n_in,
                              void* d_out, int out_size) {
    const float* x    = (const float*)d_in[0];   // [8192, 4096] fp32
    const float* cent = (const float*)d_in[1];   // [256, 1] fp32
    const int*   idx  = (const int*)d_in[2];     // [4096, 4096] int32
    float* out = (float*)d_out;                  // [8192, 4096] fp32

    void* w16_ptr = nullptr; cudaGetSymbolAddress(&w16_ptr, g_w16);
    void* x16_ptr = nullptr; cudaGetSymbolAddress(&x16_ptr, g_x16);

    prep_kernel<<<(unsigned)(NB_W + NB_X), 256>>>(cent, idx, x,
                                                  (__half*)w16_ptr, (__half*)x16_ptr);

    void* fn = nullptr;
    cudaDriverEntryPointQueryResult qr;
    cudaGetDriverEntryPointByVersion("cuTensorMapEncodeTiled", &fn, 12000,
                                     cudaEnableDefault, &qr);
    EncodeFn enc = (EncodeFn)fn;

    CUtensorMap ta, tb;
    {
        cuuint64_t dims[2]    = {IN_F, MROWS};
        cuuint64_t strides[1] = {(cuuint64_t)IN_F * 2};
        cuuint32_t box[2]     = {BK, BM};
        cuuint32_t es[2]      = {1, 1};
        enc(&ta, CU_TENSOR_MAP_DATA_TYPE_UINT16, 2, x16_ptr, dims, strides, box, es,
            CU_TENSOR_MAP_INTERLEAVE_NONE, CU_TENSOR_MAP_SWIZZLE_128B,
            CU_TENSOR_MAP_L2_PROMOTION_L2_128B, CU_TENSOR_MAP_FLOAT_OOB_FILL_NONE);
    }
    {
        cuuint64_t dims[2]    = {IN_F, OUT_F};
        cuuint64_t strides[1] = {(cuuint64_t)IN_F * 2};
        cuuint32_t box[2]     = {BK, BN};
        cuuint32_t es[2]      = {1, 1};
        enc(&tb, CU_TENSOR_MAP_DATA_TYPE_UINT16, 2, w16_ptr, dims, strides, box, es,
            CU_TENSOR_MAP_INTERLEAVE_NONE, CU_TENSOR_MAP_SWIZZLE_128B,
            CU_TENSOR_MAP_L2_PROMOTION_L2_128B, CU_TENSOR_MAP_FLOAT_OOB_FILL_NONE);
    }

    cudaFuncSetAttribute(gemm_f16, cudaFuncAttributeMaxDynamicSharedMemorySize, SMEM_BYTES);
    int grid = (MROWS / BM) * (OUT_F / BN);   // 64 * 32 = 2048
    gemm_f16<<<grid, 256, SMEM_BYTES>>>(ta, tb, out);
}